// round 4
// baseline (speedup 1.0000x reference)
#include <cuda_runtime.h>
#include <cuda_bf16.h>
#include <cstdint>

// Problem shapes (fixed by reference setup_inputs)
#define N_SEQ   256
#define M_GENES 2000
#define D_DIM   128

// Fused kernel, SMEM-staged per-warp rows for minimal loop register pressure.
//   Block: 256 threads = 8 warps. Warp w owns gene m = blockIdx.x*8 + w.
//   Tile:  32 sequence positions (blockIdx.y), matching warp size.
//
//   Prologue (per warp):
//     - 4x LDG.128: the gene's 4 embedding rows (L2-resident, 2 KB)
//     - butterfly-reduce squared norms, scale in registers
//     - park normalized rows in SMEM: smem[warp][g][lane] (2 KB/warp)
//     - lane nn loads gene_seq[n0+nn][m]
//   Inner loop (32 iters): SHFL index broadcast -> LDS.128 (uniform row,
//   conflict-free) -> STG.128 streaming store. ~12 live regs, no selects.
//   __launch_bounds__(256, 8) caps regs at 32 -> full occupancy, maximum
//   store-stream concurrency against the 262 MB HBM write wall.
__global__ void __launch_bounds__(256, 8) fused_gene_embed_kernel(
    const int* __restrict__ gene_seq,      // (N, M)
    const float* __restrict__ emb,         // (M, 4, D)
    float* __restrict__ out)               // (N, M, D)
{
    __shared__ float4 rows[8][4][32];       // 16 KB: [warp][base][lane]

    const int warp = threadIdx.x >> 5;
    const int lane = threadIdx.x & 31;
    const int m  = blockIdx.x * 8 + warp;   // grid.x = 250 (exact)
    const int n0 = blockIdx.y * 32;         // grid.y = 8   (exact)

    // ---- per-lane sequence index, issued early ----
    const int gl = gene_seq[(size_t)(n0 + lane) * M_GENES + m];

    // ---- load + normalize this gene's 4 table rows ----
    {
        const float4* src = reinterpret_cast<const float4*>(emb) + (size_t)m * 4 * 32;
        float4 r0 = src[lane];
        float4 r1 = src[32 + lane];
        float4 r2 = src[64 + lane];
        float4 r3 = src[96 + lane];

        float s0 = r0.x*r0.x + r0.y*r0.y + r0.z*r0.z + r0.w*r0.w;
        float s1 = r1.x*r1.x + r1.y*r1.y + r1.z*r1.z + r1.w*r1.w;
        float s2 = r2.x*r2.x + r2.y*r2.y + r2.z*r2.z + r2.w*r2.w;
        float s3 = r3.x*r3.x + r3.y*r3.y + r3.z*r3.z + r3.w*r3.w;
        #pragma unroll
        for (int off = 16; off > 0; off >>= 1) {
            s0 += __shfl_xor_sync(0xFFFFFFFFu, s0, off);
            s1 += __shfl_xor_sync(0xFFFFFFFFu, s1, off);
            s2 += __shfl_xor_sync(0xFFFFFFFFu, s2, off);
            s3 += __shfl_xor_sync(0xFFFFFFFFu, s3, off);
        }
        const float i0 = 1.0f / fmaxf(sqrtf(s0), 1e-12f);
        const float i1 = 1.0f / fmaxf(sqrtf(s1), 1e-12f);
        const float i2 = 1.0f / fmaxf(sqrtf(s2), 1e-12f);
        const float i3 = 1.0f / fmaxf(sqrtf(s3), 1e-12f);
        r0.x *= i0; r0.y *= i0; r0.z *= i0; r0.w *= i0;
        r1.x *= i1; r1.y *= i1; r1.z *= i1; r1.w *= i1;
        r2.x *= i2; r2.y *= i2; r2.z *= i2; r2.w *= i2;
        r3.x *= i3; r3.y *= i3; r3.z *= i3; r3.w *= i3;

        rows[warp][0][lane] = r0;
        rows[warp][1][lane] = r1;
        rows[warp][2][lane] = r2;
        rows[warp][3][lane] = r3;
    }
    __syncwarp();   // warp-private smem slab: warp-level sync suffices

    // ---- pure streaming-store loop ----
    float4* ob = reinterpret_cast<float4*>(out)
               + ((size_t)n0 * M_GENES + m) * 32 + lane;
    const size_t row_stride = (size_t)M_GENES * 32;   // one n step

    #pragma unroll 8
    for (int nn = 0; nn < 32; nn++) {
        const int g = __shfl_sync(0xFFFFFFFFu, gl, nn);
        const float4 v = rows[warp][g][lane];          // uniform row, LDS.128
        __stcs(ob, v);
        ob += row_stride;
    }
}

extern "C" void kernel_launch(void* const* d_in, const int* in_sizes, int n_in,
                              void* d_out, int out_size) {
    const int* gene_seq = (const int*)d_in[0];      // (256, 2000) int32
    const float* emb    = (const float*)d_in[1];    // (2000, 4, 128) fp32
    float* out          = (float*)d_out;            // (256, 2000, 128) fp32

    dim3 grid(M_GENES / 8, N_SEQ / 32, 1);          // (250, 8)
    fused_gene_embed_kernel<<<grid, 256>>>(gene_seq, emb, out);
}

// round 5
// speedup vs baseline: 1.0316x; 1.0316x over previous
#include <cuda_runtime.h>
#include <cuda_bf16.h>
#include <cstdint>

// Problem shapes (fixed by reference setup_inputs)
#define N_SEQ   256
#define M_GENES 2000
#define D_DIM   128

// Fused kernel, register-resident rows (R3 structure), 2 n-tiles per warp.
//   Block: 256 threads = 8 warps. Warp w owns gene m = blockIdx.x*8 + w.
//   Tile:  2 x 32 sequence positions (blockIdx.y selects a 64-row slab).
//
//   Prologue (per warp, registers only):
//     - 4x LDG.128: the gene's 4 embedding rows (L2-resident, 2 KB)
//     - butterfly-reduce squared norms, scale rows in registers (16 regs)
//     - lane nn holds gene_seq for both tiles (2 x 4B LDG)
//   Inner loop (32 iters): 2x { shfl broadcast, 4-way reg select,
//   streaming STG.128 }. Two independent store chains per iteration.
__global__ void __launch_bounds__(256) fused_gene_embed_kernel(
    const int* __restrict__ gene_seq,      // (N, M)
    const float* __restrict__ emb,         // (M, 4, D)
    float* __restrict__ out)               // (N, M, D)
{
    const int warp = threadIdx.x >> 5;
    const int lane = threadIdx.x & 31;
    const int m  = blockIdx.x * 8 + warp;   // grid.x = 250 (exact)
    const int n0 = blockIdx.y * 64;         // grid.y = 4   (exact)

    // ---- per-lane sequence indices for the two 32-row tiles ----
    const int glA = gene_seq[(size_t)(n0 + lane)      * M_GENES + m];
    const int glB = gene_seq[(size_t)(n0 + 32 + lane) * M_GENES + m];

    // ---- load this gene's 4 table rows into registers ----
    const float4* src = reinterpret_cast<const float4*>(emb) + (size_t)m * 4 * 32;
    float4 r0 = src[lane];
    float4 r1 = src[32 + lane];
    float4 r2 = src[64 + lane];
    float4 r3 = src[96 + lane];

    // ---- normalize rows in registers (butterfly keeps norm in all lanes) ----
    {
        float s0 = r0.x*r0.x + r0.y*r0.y + r0.z*r0.z + r0.w*r0.w;
        float s1 = r1.x*r1.x + r1.y*r1.y + r1.z*r1.z + r1.w*r1.w;
        float s2 = r2.x*r2.x + r2.y*r2.y + r2.z*r2.z + r2.w*r2.w;
        float s3 = r3.x*r3.x + r3.y*r3.y + r3.z*r3.z + r3.w*r3.w;
        #pragma unroll
        for (int off = 16; off > 0; off >>= 1) {
            s0 += __shfl_xor_sync(0xFFFFFFFFu, s0, off);
            s1 += __shfl_xor_sync(0xFFFFFFFFu, s1, off);
            s2 += __shfl_xor_sync(0xFFFFFFFFu, s2, off);
            s3 += __shfl_xor_sync(0xFFFFFFFFu, s3, off);
        }
        const float i0 = 1.0f / fmaxf(sqrtf(s0), 1e-12f);
        const float i1 = 1.0f / fmaxf(sqrtf(s1), 1e-12f);
        const float i2 = 1.0f / fmaxf(sqrtf(s2), 1e-12f);
        const float i3 = 1.0f / fmaxf(sqrtf(s3), 1e-12f);
        r0.x *= i0; r0.y *= i0; r0.z *= i0; r0.w *= i0;
        r1.x *= i1; r1.y *= i1; r1.z *= i1; r1.w *= i1;
        r2.x *= i2; r2.y *= i2; r2.z *= i2; r2.w *= i2;
        r3.x *= i3; r3.y *= i3; r3.z *= i3; r3.w *= i3;
    }

    // ---- two interleaved streaming-store chains ----
    const size_t row_stride = (size_t)M_GENES * 32;   // one n step (float4 units)
    float4* obA = reinterpret_cast<float4*>(out)
                + ((size_t)n0 * M_GENES + m) * 32 + lane;
    float4* obB = obA + row_stride * 32;

    #pragma unroll 8
    for (int nn = 0; nn < 32; nn++) {
        const int gA = __shfl_sync(0xFFFFFFFFu, glA, nn);
        const int gB = __shfl_sync(0xFFFFFFFFu, glB, nn);
        const float4 vA = (gA == 0) ? r0 : (gA == 1) ? r1 : (gA == 2) ? r2 : r3;
        const float4 vB = (gB == 0) ? r0 : (gB == 1) ? r1 : (gB == 2) ? r2 : r3;
        __stcs(obA, vA);
        __stcs(obB, vB);
        obA += row_stride;
        obB += row_stride;
    }
}

extern "C" void kernel_launch(void* const* d_in, const int* in_sizes, int n_in,
                              void* d_out, int out_size) {
    const int* gene_seq = (const int*)d_in[0];      // (256, 2000) int32
    const float* emb    = (const float*)d_in[1];    // (2000, 4, 128) fp32
    float* out          = (float*)d_out;            // (256, 2000, 128) fp32

    dim3 grid(M_GENES / 8, N_SEQ / 64, 1);          // (250, 4)
    fused_gene_embed_kernel<<<grid, 256>>>(gene_seq, emb, out);
}